// round 1
// baseline (speedup 1.0000x reference)
#include <cuda_runtime.h>

#define NN 100000
#define NE 1600000
#define NB_SCAN ((NN + 255) / 256)   // 391

// ---------------- scratch (static __device__ — no allocations) ----------------
__device__ int   g_deg[NN];
__device__ int   g_cursor[NN];
__device__ float g_dinv[NN];
__device__ int   g_offs[NN + 1];
__device__ int   g_csrc[NE];
__device__ int   g_bsum[512];
__device__ int   g_flag;                 // !=0 -> edge_index stored as int32
__device__ float g_y [(size_t)NN * 64];
__device__ float g_h [(size_t)NN * 64];
__device__ float g_y3[(size_t)NN * 16];

__device__ __forceinline__ float* bufsel(int s, float* ext) {
    if (s == 0) return g_y;
    if (s == 1) return g_h;
    if (s == 2) return g_y3;
    return ext;
}

// ---------------- init / dtype detect ----------------
__global__ void k_zero() {
    int i = blockIdx.x * blockDim.x + threadIdx.x;
    if (i < NN) { g_deg[i] = 0; g_cursor[i] = 0; }
    if (i == 0) g_flag = 0;
}

// If data is int64 (values in [0,100000)), every odd 32-bit word is 0.
// If data is int32, odd words are real indices (all-zero prob ~ 0).
__global__ void k_detect(const int* __restrict__ w) {
    int t = threadIdx.x;
    int f = 0;
    for (int i = t; i < 2048; i += 256)
        if (w[2 * i + 1] != 0) f = 1;
    if (f) atomicOr(&g_flag, 1);
}

__device__ __forceinline__ int edge_val(const int* __restrict__ w, int elem, bool i32) {
    return i32 ? w[elem] : w[2 * elem];
}

// ---------------- CSR build ----------------
__global__ void k_hist(const int* __restrict__ w) {
    bool i32 = (g_flag != 0);
    int stride = gridDim.x * blockDim.x;
    for (int e = blockIdx.x * blockDim.x + threadIdx.x; e < NE; e += stride) {
        int d = edge_val(w, NE + e, i32);
        atomicAdd(&g_deg[d], 1);
    }
}

__global__ void k_dinv() {
    int i = blockIdx.x * blockDim.x + threadIdx.x;
    if (i < NN) g_dinv[i] = rsqrtf((float)(g_deg[i] + 1));  // +1 self loop
}

__global__ void k_scan1() {
    __shared__ int s[256];
    int t = threadIdx.x;
    int i = blockIdx.x * 256 + t;
    int v = (i < NN) ? g_deg[i] : 0;
    s[t] = v;
    __syncthreads();
    for (int o = 1; o < 256; o <<= 1) {
        int u = (t >= o) ? s[t - o] : 0;
        __syncthreads();
        s[t] += u;
        __syncthreads();
    }
    if (i < NN) g_offs[i] = s[t] - v;           // exclusive within block
    if (t == 255) g_bsum[blockIdx.x] = s[255];  // block total
}

__global__ void k_scan2() {
    __shared__ int s[512];
    int t = threadIdx.x;
    int v = (t < NB_SCAN) ? g_bsum[t] : 0;
    s[t] = v;
    __syncthreads();
    for (int o = 1; o < 512; o <<= 1) {
        int u = (t >= o) ? s[t - o] : 0;
        __syncthreads();
        s[t] += u;
        __syncthreads();
    }
    g_bsum[t] = s[t] - v;  // exclusive block offsets
}

__global__ void k_scan3() {
    int i = blockIdx.x * 256 + threadIdx.x;
    if (i < NN) g_offs[i] += g_bsum[blockIdx.x];
    if (i == 0) g_offs[NN] = NE;
}

__global__ void k_scatter(const int* __restrict__ w) {
    bool i32 = (g_flag != 0);
    int stride = gridDim.x * blockDim.x;
    for (int e = blockIdx.x * blockDim.x + threadIdx.x; e < NE; e += stride) {
        int s = edge_val(w, e, i32);
        int d = edge_val(w, NE + e, i32);
        int pos = g_offs[d] + atomicAdd(&g_cursor[d], 1);
        g_csrc[pos] = s;
    }
}

// ---------------- linear: Y = dinv ⊙ (X @ W) ----------------
template <int IN, int OUT>
__global__ void k_linear(const float* Xext, const float* __restrict__ W,
                         int xsel, int ysel) {
    constexpr int CG   = OUT / 4;    // float4 groups per row
    constexpr int ROWS = 256 / CG;   // rows per block
    const float* X = (xsel < 0) ? Xext : (const float*)bufsel(xsel, nullptr);
    float*       Y = bufsel(ysel, nullptr);

    __shared__ float4 Ws[IN * CG];
    __shared__ float  Xs[ROWS * IN];
    int t = threadIdx.x;

    for (int i = t; i < IN * CG; i += 256)
        Ws[i] = ((const float4*)W)[i];

    int row0 = blockIdx.x * ROWS;
    for (int i = t; i < ROWS * IN; i += 256) {
        int r = i / IN, c = i % IN;
        int gr = row0 + r;
        Xs[i] = (gr < NN) ? X[(size_t)gr * IN + c] : 0.f;
    }
    __syncthreads();

    int r = t / CG, cg = t % CG;
    int grow = row0 + r;
    float4 acc = make_float4(0.f, 0.f, 0.f, 0.f);
#pragma unroll 16
    for (int k = 0; k < IN; k++) {
        float  xv = Xs[r * IN + k];
        float4 w4 = Ws[k * CG + cg];
        acc.x = fmaf(xv, w4.x, acc.x);
        acc.y = fmaf(xv, w4.y, acc.y);
        acc.z = fmaf(xv, w4.z, acc.z);
        acc.w = fmaf(xv, w4.w, acc.w);
    }
    if (grow < NN) {
        float dv = g_dinv[grow];
        float4 o = make_float4(acc.x * dv, acc.y * dv, acc.z * dv, acc.w * dv);
        ((float4*)Y)[(size_t)grow * CG + cg] = o;
    }
}

// ---------------- aggregation: O[i] = act(dinv[i]*(Σ_nbr Y[src] + Y[i]) + b) ----------------
template <int OUT, bool RELU>
__global__ void k_agg(const float* __restrict__ bias, float* Oext,
                      int ysel, int osel) {
    constexpr int L   = OUT / 4;   // lanes per node
    constexpr int NPB = 256 / L;   // nodes per block
    const float4* Y4 = (const float4*)bufsel(ysel, nullptr);
    float4*       O4 = (float4*)bufsel(osel, Oext);

    int t    = threadIdx.x;
    int node = blockIdx.x * NPB + t / L;
    if (node >= NN) return;
    int lane = t % L;

    float4 acc = Y4[(size_t)node * L + lane];  // self loop term
    int p = g_offs[node], end = g_offs[node + 1];
    int sN = (p < end) ? g_csrc[p] : 0;        // prefetch next src index
    while (p < end) {
        int s = sN;
        ++p;
        if (p < end) sN = g_csrc[p];
        float4 v = Y4[(size_t)s * L + lane];
        acc.x += v.x; acc.y += v.y; acc.z += v.z; acc.w += v.w;
    }
    float  dv = g_dinv[node];
    float4 bb = ((const float4*)bias)[lane];
    float4 o;
    o.x = fmaf(acc.x, dv, bb.x);
    o.y = fmaf(acc.y, dv, bb.y);
    o.z = fmaf(acc.z, dv, bb.z);
    o.w = fmaf(acc.w, dv, bb.w);
    if (RELU) {
        o.x = fmaxf(o.x, 0.f); o.y = fmaxf(o.y, 0.f);
        o.z = fmaxf(o.z, 0.f); o.w = fmaxf(o.w, 0.f);
    }
    O4[(size_t)node * L + lane] = o;
}

// ---------------- launch ----------------
extern "C" void kernel_launch(void* const* d_in, const int* in_sizes, int n_in,
                              void* d_out, int out_size) {
    const float* x  = (const float*)d_in[0];
    const int*   ei = (const int*)d_in[1];
    const float* W1 = (const float*)d_in[2];
    const float* b1 = (const float*)d_in[3];
    const float* W2 = (const float*)d_in[4];
    const float* b2 = (const float*)d_in[5];
    const float* W3 = (const float*)d_in[6];
    const float* b3 = (const float*)d_in[7];
    float* out = (float*)d_out;

    // graph preprocessing (once per launch, reused by all 3 layers)
    k_zero   <<<NB_SCAN, 256>>>();
    k_detect <<<1,       256>>>(ei);
    k_hist   <<<1024,    256>>>(ei);
    k_dinv   <<<NB_SCAN, 256>>>();
    k_scan1  <<<NB_SCAN, 256>>>();
    k_scan2  <<<1,       512>>>();
    k_scan3  <<<NB_SCAN, 256>>>();
    k_scatter<<<1024,    256>>>(ei);

    // layer 1: 128 -> 64
    k_linear<128, 64><<<NN / 16, 256>>>(x, W1, -1, 0);        // x @ W1 -> g_y
    k_agg<64, true> <<<NN / 16, 256>>>(b1, nullptr, 0, 1);     // agg -> g_h (relu)
    // layer 2: 64 -> 64
    k_linear<64, 64><<<NN / 16, 256>>>(nullptr, W2, 1, 0);     // g_h @ W2 -> g_y
    k_agg<64, true> <<<NN / 16, 256>>>(b2, nullptr, 0, 1);     // agg -> g_h (relu)
    // layer 3: 64 -> 16
    k_linear<64, 16><<<(NN + 63) / 64, 256>>>(nullptr, W3, 1, 2);  // g_h @ W3 -> g_y3
    k_agg<16, false><<<(NN + 63) / 64, 256>>>(b3, out, 2, -9);     // agg -> d_out
}

// round 2
// speedup vs baseline: 1.3987x; 1.3987x over previous
#include <cuda_runtime.h>

#define NN 100000
#define NE 1600000
#define NB_SCAN ((NN + 255) / 256)   // 391

// ---------------- scratch (static __device__ — no allocations) ----------------
__device__ int   g_deg[NN];
__device__ int   g_cur[NN];
__device__ float g_dinv[NN];
__device__ int   g_offs[NN + 1];
__device__ int   g_csrc[NE];
__device__ int   g_bsum[512];
__device__ int   g_flag;                 // !=0 -> edge_index stored as int32
__device__ float g_y [NN * 64];
__device__ float g_h [NN * 64];
__device__ float g_y3[NN * 16];

__device__ __forceinline__ float* bufsel(int s, float* ext) {
    if (s == 0) return g_y;
    if (s == 1) return g_h;
    if (s == 2) return g_y3;
    return ext;
}

// ---------------- dtype detect ----------------
// int64 indices < 100000 have zero high words; int32 data has nonzero odd words.
__global__ void k_detect(const int* __restrict__ w) {
    __shared__ int sf;
    int t = threadIdx.x;
    if (t == 0) sf = 0;
    __syncthreads();
    int f = 0;
    for (int i = t; i < 2048; i += 256)
        if (w[2 * i + 1] != 0) f = 1;
    if (f) atomicOr(&sf, 1);
    __syncthreads();
    if (t == 0) g_flag = sf;
}

__device__ __forceinline__ int edge_val(const int* __restrict__ w, int elem, bool i32) {
    return i32 ? w[elem] : w[2 * elem];
}

// ---------------- CSR build ----------------
__global__ void k_hist(const int* __restrict__ w) {
    bool i32 = (g_flag != 0);
    int stride = gridDim.x * blockDim.x;
    for (int e = blockIdx.x * blockDim.x + threadIdx.x; e < NE; e += stride) {
        int d = edge_val(w, NE + e, i32);
        atomicAdd(&g_deg[d], 1);
    }
}

// block-local exclusive scan of deg; also emits dinv
__global__ void k_scan1() {
    __shared__ int s[256];
    int t = threadIdx.x;
    int i = blockIdx.x * 256 + t;
    int v = (i < NN) ? g_deg[i] : 0;
    if (i < NN) g_dinv[i] = rsqrtf((float)(v + 1));   // +1 self loop
    s[t] = v;
    __syncthreads();
    for (int o = 1; o < 256; o <<= 1) {
        int u = (t >= o) ? s[t - o] : 0;
        __syncthreads();
        s[t] += u;
        __syncthreads();
    }
    if (i < NN) g_offs[i] = s[t] - v;           // exclusive within block
    if (t == 255) g_bsum[blockIdx.x] = s[255];  // block total
}

__global__ void k_scan2() {
    __shared__ int s[512];
    int t = threadIdx.x;
    int v = (t < NB_SCAN) ? g_bsum[t] : 0;
    s[t] = v;
    __syncthreads();
    for (int o = 1; o < 512; o <<= 1) {
        int u = (t >= o) ? s[t - o] : 0;
        __syncthreads();
        s[t] += u;
        __syncthreads();
    }
    g_bsum[t] = s[t] - v;  // exclusive block offsets
}

// add block offsets; init write cursors = offsets
__global__ void k_scan3() {
    int i = blockIdx.x * 256 + threadIdx.x;
    if (i < NN) {
        int o = g_offs[i] + g_bsum[blockIdx.x];
        g_offs[i] = o;
        g_cur[i]  = o;
    }
    if (i == 0) g_offs[NN] = NE;
}

__global__ void k_scatter(const int* __restrict__ w) {
    bool i32 = (g_flag != 0);
    int stride = gridDim.x * blockDim.x;
    for (int e = blockIdx.x * blockDim.x + threadIdx.x; e < NE; e += stride) {
        int s = edge_val(w, e, i32);
        int d = edge_val(w, NE + e, i32);
        int pos = atomicAdd(&g_cur[d], 1);
        g_csrc[pos] = s;
    }
}

// ---------------- linear: Y = dinv ⊙ (X @ W), register-blocked R=4 ----------------
template <int IN, int OUT>
__global__ void k_linear(const float* Xext, const float* __restrict__ W,
                         int xsel, int ysel) {
    constexpr int CG   = OUT / 4;        // float4 groups per row
    constexpr int R    = 4;              // rows per thread
    constexpr int ROWS = (256 / CG) * R; // rows per block
    const float* X = (xsel < 0) ? Xext : (const float*)bufsel(xsel, nullptr);
    float*       Y = bufsel(ysel, nullptr);

    extern __shared__ float smem[];
    float*  Xs = smem;                       // ROWS * IN floats
    float4* Ws = (float4*)(smem + ROWS * IN);  // IN * CG float4s

    int t = threadIdx.x;
    for (int i = t; i < IN * CG; i += 256)
        Ws[i] = ((const float4*)W)[i];

    int row0 = blockIdx.x * ROWS;
    for (int i = t; i < ROWS * IN; i += 256) {
        int r = i / IN, c = i % IN;
        int gr = row0 + r;
        Xs[i] = (gr < NN) ? X[gr * IN + c] : 0.f;
    }
    __syncthreads();

    int cg = t % CG;
    int rb = (t / CG) * R;                 // first local row for this thread
    float4 acc[R];
#pragma unroll
    for (int j = 0; j < R; j++) acc[j] = make_float4(0.f, 0.f, 0.f, 0.f);

#pragma unroll 8
    for (int k = 0; k < IN; k++) {
        float4 w4 = Ws[k * CG + cg];
#pragma unroll
        for (int j = 0; j < R; j++) {
            float xv = Xs[(rb + j) * IN + k];
            acc[j].x = fmaf(xv, w4.x, acc[j].x);
            acc[j].y = fmaf(xv, w4.y, acc[j].y);
            acc[j].z = fmaf(xv, w4.z, acc[j].z);
            acc[j].w = fmaf(xv, w4.w, acc[j].w);
        }
    }
#pragma unroll
    for (int j = 0; j < R; j++) {
        int grow = row0 + rb + j;
        if (grow < NN) {
            float dv = g_dinv[grow];
            float4 o = make_float4(acc[j].x * dv, acc[j].y * dv,
                                   acc[j].z * dv, acc[j].w * dv);
            ((float4*)Y)[grow * CG + cg] = o;
        }
    }
}

// ---------------- aggregation: O[i] = act(dinv[i]*(Σ_nbr Y[src] + Y[i]) + b) ----------------
template <int OUT, bool RELU>
__global__ void k_agg(const float* __restrict__ bias, float* Oext,
                      int ysel, int osel) {
    constexpr int L   = OUT / 4;   // lanes per node
    constexpr int NPB = 256 / L;   // nodes per block
    const float4* __restrict__ Y4 = (const float4*)bufsel(ysel, nullptr);
    float4*       O4 = (float4*)bufsel(osel, Oext);

    int t    = threadIdx.x;
    int node = blockIdx.x * NPB + t / L;
    if (node >= NN) return;
    int lane = t % L;

    float4 acc = Y4[node * L + lane];  // self loop term
    int p = g_offs[node], end = g_offs[node + 1];
    const int* __restrict__ cs = g_csrc;

    // 4-wide unroll: 4 gathers in flight per node stream
    for (; p + 4 <= end; p += 4) {
        int s0 = cs[p], s1 = cs[p + 1], s2 = cs[p + 2], s3 = cs[p + 3];
        float4 v0 = Y4[s0 * L + lane];
        float4 v1 = Y4[s1 * L + lane];
        float4 v2 = Y4[s2 * L + lane];
        float4 v3 = Y4[s3 * L + lane];
        acc.x += (v0.x + v1.x) + (v2.x + v3.x);
        acc.y += (v0.y + v1.y) + (v2.y + v3.y);
        acc.z += (v0.z + v1.z) + (v2.z + v3.z);
        acc.w += (v0.w + v1.w) + (v2.w + v3.w);
    }
    for (; p < end; ++p) {
        float4 v = Y4[cs[p] * L + lane];
        acc.x += v.x; acc.y += v.y; acc.z += v.z; acc.w += v.w;
    }

    float  dv = g_dinv[node];
    float4 bb = ((const float4*)bias)[lane];
    float4 o;
    o.x = fmaf(acc.x, dv, bb.x);
    o.y = fmaf(acc.y, dv, bb.y);
    o.z = fmaf(acc.z, dv, bb.z);
    o.w = fmaf(acc.w, dv, bb.w);
    if (RELU) {
        o.x = fmaxf(o.x, 0.f); o.y = fmaxf(o.y, 0.f);
        o.z = fmaxf(o.z, 0.f); o.w = fmaxf(o.w, 0.f);
    }
    O4[node * L + lane] = o;
}

// ---------------- launch ----------------
extern "C" void kernel_launch(void* const* d_in, const int* in_sizes, int n_in,
                              void* d_out, int out_size) {
    const float* x  = (const float*)d_in[0];
    const int*   ei = (const int*)d_in[1];
    const float* W1 = (const float*)d_in[2];
    const float* b1 = (const float*)d_in[3];
    const float* W2 = (const float*)d_in[4];
    const float* b2 = (const float*)d_in[5];
    const float* W3 = (const float*)d_in[6];
    const float* b3 = (const float*)d_in[7];
    float* out = (float*)d_out;

    // dynamic smem sizes per linear instantiation
    constexpr int SM1 = (64 * 128 + 128 * 16 * 4) * 4;   // 65536
    constexpr int SM2 = (64 * 64 + 64 * 16 * 4) * 4;     // 32768
    constexpr int SM3 = (256 * 64 + 64 * 4 * 4) * 4;     // 69632
    cudaFuncSetAttribute(k_linear<128, 64>, cudaFuncAttributeMaxDynamicSharedMemorySize, SM1);
    cudaFuncSetAttribute(k_linear<64, 64>,  cudaFuncAttributeMaxDynamicSharedMemorySize, SM2);
    cudaFuncSetAttribute(k_linear<64, 16>,  cudaFuncAttributeMaxDynamicSharedMemorySize, SM3);

    void* degp = nullptr;
    cudaGetSymbolAddress(&degp, g_deg);
    cudaMemsetAsync(degp, 0, NN * sizeof(int));

    // graph preprocessing (once per launch, reused by all 3 layers)
    k_detect <<<1,       256>>>(ei);
    k_hist   <<<1024,    256>>>(ei);
    k_scan1  <<<NB_SCAN, 256>>>();
    k_scan2  <<<1,       512>>>();
    k_scan3  <<<NB_SCAN, 256>>>();
    k_scatter<<<1024,    256>>>(ei);

    // layer 1: 128 -> 64   (64 rows/block)
    k_linear<128, 64><<<(NN + 63) / 64, 256, SM1>>>(x, W1, -1, 0);
    k_agg<64, true>  <<<NN / 16, 256>>>(b1, nullptr, 0, 1);
    // layer 2: 64 -> 64
    k_linear<64, 64> <<<(NN + 63) / 64, 256, SM2>>>(nullptr, W2, 1, 0);
    k_agg<64, true>  <<<NN / 16, 256>>>(b2, nullptr, 0, 1);
    // layer 3: 64 -> 16    (256 rows/block)
    k_linear<64, 16> <<<(NN + 255) / 256, 256, SM3>>>(nullptr, W3, 1, 2);
    k_agg<16, false> <<<(NN + 63) / 64, 256>>>(b3, out, 2, -9);
}